// round 15
// baseline (speedup 1.0000x reference)
#include <cuda_runtime.h>

#define BATCH 16
#define NPIX (1024 * 1024)
#define NVEC (NPIX / 4)
#define NV8  (NPIX / 8)
#define NACC 21
#define BPG 2                     // pipeline group size: <=48 MB evict_last live set
#define NGROUP (BATCH / BPG)      // 8 groups
#define TPB 256
#define GXC 111                   // combined: blocks per batch per role (1:1 split)

// Scratch (allocation-free per harness rules)
__device__ double g_acc[BATCH][NACC];

__global__ void zero_kernel() {
    int i = blockIdx.x * blockDim.x + threadIdx.x;
    if (i < BATCH * NACC) ((double*)g_acc)[i] = 0.0;
}

// 256-bit loads with L2 eviction priority (sm_103 requires .v8.b32 for these hints)
struct f8 { float4 a, b; };

__device__ __forceinline__ f8 ld8_last(const float* p) {   // pin in L2
    f8 v;
    asm("ld.global.L2::evict_last.v8.b32 {%0,%1,%2,%3,%4,%5,%6,%7}, [%8];"
        : "=f"(v.a.x), "=f"(v.a.y), "=f"(v.a.z), "=f"(v.a.w),
          "=f"(v.b.x), "=f"(v.b.y), "=f"(v.b.z), "=f"(v.b.w)
        : "l"(p));
    return v;
}
__device__ __forceinline__ f8 ld8_first(const float* p) {  // stream through L2
    f8 v;
    asm("ld.global.L2::evict_first.v8.b32 {%0,%1,%2,%3,%4,%5,%6,%7}, [%8];"
        : "=f"(v.a.x), "=f"(v.a.y), "=f"(v.a.z), "=f"(v.a.w),
          "=f"(v.b.x), "=f"(v.b.y), "=f"(v.b.z), "=f"(v.b.w)
        : "l"(p));
    return v;
}

// ---------------- device bodies ----------------

__device__ __forceinline__ void reduce_body(const float* __restrict__ src,
                                            const float* __restrict__ dst,
                                            int b, int blk, int nblk, int tid) {
    const float* A0 = src + (size_t)b * 3 * NPIX;
    const float* A1 = A0 + NPIX;
    const float* A2 = A1 + NPIX;
    const float* B0 = dst + (size_t)b * 3 * NPIX;
    const float* B1 = B0 + NPIX;
    const float* B2 = B1 + NPIX;

    float acc[NACC];
#pragma unroll
    for (int k = 0; k < NACC; k++) acc[k] = 0.0f;

    const int stride = nblk * TPB;
    for (int i = blk * TPB + tid; i < NV8; i += stride) {
        const int e = i * 8;
        f8 a0 = ld8_last(A0 + e), a1 = ld8_last(A1 + e), a2 = ld8_last(A2 + e);
        f8 b0 = ld8_first(B0 + e), b1 = ld8_first(B1 + e), b2 = ld8_first(B2 + e);
#define LANE(h, c)                                                              \
        {                                                                       \
            float x0 = a0.h.c, x1 = a1.h.c, x2 = a2.h.c;                        \
            float y0 = b0.h.c, y1 = b1.h.c, y2 = b2.h.c;                        \
            acc[0] += x0;  acc[1] += x1;  acc[2] += x2;                         \
            acc[3] += y0;  acc[4] += y1;  acc[5] += y2;                         \
            acc[6]  += x0 * x0; acc[7]  += x0 * x1; acc[8]  += x0 * x2;         \
            acc[9]  += x1 * x1; acc[10] += x1 * x2; acc[11] += x2 * x2;         \
            acc[12] += y0 * x0; acc[13] += y0 * x1; acc[14] += y0 * x2;         \
            acc[15] += y1 * x0; acc[16] += y1 * x1; acc[17] += y1 * x2;         \
            acc[18] += y2 * x0; acc[19] += y2 * x1; acc[20] += y2 * x2;         \
        }
        LANE(a, x) LANE(a, y) LANE(a, z) LANE(a, w)
        LANE(b, x) LANE(b, y) LANE(b, z) LANE(b, w)
#undef LANE
    }

    __shared__ float s[NACC][TPB / 32];
    const int lane = tid & 31;
    const int warp = tid >> 5;
#pragma unroll
    for (int k = 0; k < NACC; k++) {
        float v = acc[k];
#pragma unroll
        for (int o = 16; o > 0; o >>= 1) v += __shfl_down_sync(0xffffffffu, v, o);
        if (lane == 0) s[k][warp] = v;
    }
    __syncthreads();
    if (tid < NACC) {
        float v = 0.0f;
#pragma unroll
        for (int w = 0; w < TPB / 32; w++) v += s[tid][w];
        atomicAdd(&g_acc[b][tid], (double)v);
    }
}

__device__ __forceinline__ void apply_body(const float* __restrict__ src,
                                           float* __restrict__ out,
                                           int b, int blk, int nblk, int tid) {
    __shared__ float sh_coef[12];
    if (tid == 0) {
        const double* a = g_acc[b];
        const double n = (double)NPIX;
        double mA[3] = {a[0] / n, a[1] / n, a[2] / n};
        double mB[3] = {a[3] / n, a[4] / n, a[5] / n};
        double AA[3][3];
        AA[0][0] = a[6]  - n * mA[0] * mA[0] + 0.001;
        AA[0][1] = a[7]  - n * mA[0] * mA[1];
        AA[0][2] = a[8]  - n * mA[0] * mA[2];
        AA[1][1] = a[9]  - n * mA[1] * mA[1] + 0.001;
        AA[1][2] = a[10] - n * mA[1] * mA[2];
        AA[2][2] = a[11] - n * mA[2] * mA[2] + 0.001;
        AA[1][0] = AA[0][1]; AA[2][0] = AA[0][2]; AA[2][1] = AA[1][2];
        double BA[3][3];
#pragma unroll
        for (int i = 0; i < 3; i++)
#pragma unroll
            for (int j = 0; j < 3; j++)
                BA[i][j] = a[12 + 3 * i + j] - n * mB[i] * mA[j];

        double c00 =  (AA[1][1] * AA[2][2] - AA[1][2] * AA[2][1]);
        double c01 = -(AA[1][0] * AA[2][2] - AA[1][2] * AA[2][0]);
        double c02 =  (AA[1][0] * AA[2][1] - AA[1][1] * AA[2][0]);
        double c10 = -(AA[0][1] * AA[2][2] - AA[0][2] * AA[2][1]);
        double c11 =  (AA[0][0] * AA[2][2] - AA[0][2] * AA[2][0]);
        double c12 = -(AA[0][0] * AA[2][1] - AA[0][1] * AA[2][0]);
        double c20 =  (AA[0][1] * AA[1][2] - AA[0][2] * AA[1][1]);
        double c21 = -(AA[0][0] * AA[1][2] - AA[0][2] * AA[1][0]);
        double c22 =  (AA[0][0] * AA[1][1] - AA[0][1] * AA[1][0]);
        double det = AA[0][0] * c00 + AA[0][1] * c01 + AA[0][2] * c02;
        double id = 1.0 / det;
        double inv[3][3] = {{c00 * id, c10 * id, c20 * id},
                            {c01 * id, c11 * id, c21 * id},
                            {c02 * id, c12 * id, c22 * id}};
#pragma unroll
        for (int i = 0; i < 3; i++) {
            double xi[3];
#pragma unroll
            for (int j = 0; j < 3; j++)
                xi[j] = BA[i][0] * inv[0][j] + BA[i][1] * inv[1][j] + BA[i][2] * inv[2][j];
            sh_coef[3 * i + 0] = (float)xi[0];
            sh_coef[3 * i + 1] = (float)xi[1];
            sh_coef[3 * i + 2] = (float)xi[2];
            sh_coef[9 + i] = (float)(mB[i] - (xi[0] * mA[0] + xi[1] * mA[1] + xi[2] * mA[2]));
        }
    }
    __syncthreads();

    const float x00 = sh_coef[0], x01 = sh_coef[1], x02 = sh_coef[2];
    const float x10 = sh_coef[3], x11 = sh_coef[4], x12 = sh_coef[5];
    const float x20 = sh_coef[6], x21 = sh_coef[7], x22 = sh_coef[8];
    const float o0 = sh_coef[9], o1 = sh_coef[10], o2 = sh_coef[11];

    const float4* A0 = (const float4*)(src + (size_t)b * 3 * NPIX);
    const float4* A1 = A0 + NVEC;
    const float4* A2 = A1 + NVEC;
    float4* O0 = (float4*)(out + (size_t)b * 3 * NPIX);
    float4* O1 = O0 + NVEC;
    float4* O2 = O1 + NVEC;

    const int stride = nblk * TPB;
    for (int i = blk * TPB + tid; i < NVEC; i += stride) {
        // src pinned by the previous launch's evict_last loads; .cs demotes on use
        float4 a0 = __ldcs(A0 + i), a1 = __ldcs(A1 + i), a2 = __ldcs(A2 + i);
        float4 r0, r1, r2;
#define LANE(c)                                                \
        r0.c = x00 * a0.c + x01 * a1.c + x02 * a2.c + o0;      \
        r1.c = x10 * a0.c + x11 * a1.c + x12 * a2.c + o1;      \
        r2.c = x20 * a0.c + x21 * a1.c + x22 * a2.c + o2;
        LANE(x) LANE(y) LANE(z) LANE(w)
#undef LANE
        __stcs(O0 + i, r0);
        __stcs(O1 + i, r1);
        __stcs(O2 + i, r2);
    }
}

// ---------------- kernels ----------------

// Prologue: reduce group 0 only.
__global__ void __launch_bounds__(TPB, 3) reduce_kernel(const float* __restrict__ src,
                                                        const float* __restrict__ dst,
                                                        int base) {
    reduce_body(src, dst, base + blockIdx.y, blockIdx.x, (int)gridDim.x, threadIdx.x);
}

// Pipelined stage, 1:1 block split. grid = (222, 2) = 444 blocks = 3/SM wave.
//   y = 0 : apply batches base, base+1   (111 blocks each, v4, ~9.2 iters)
//   y = 1 : reduce batches base+2,base+3 (111 blocks each, v8, ~4.6 iters)
__global__ void __launch_bounds__(TPB, 3) combined_kernel(const float* __restrict__ src,
                                                          const float* __restrict__ dst,
                                                          float* __restrict__ out,
                                                          int base) {
    const int half = (blockIdx.x >= GXC) ? 1 : 0;
    const int blk  = blockIdx.x - half * GXC;
    if (blockIdx.y == 0) {
        apply_body(src, out, base + half, blk, GXC, threadIdx.x);
    } else {
        reduce_body(src, dst, base + BPG + half, blk, GXC, threadIdx.x);
    }
}

// Epilogue: apply final group.
__global__ void __launch_bounds__(TPB, 3) apply_kernel(const float* __restrict__ src,
                                                       float* __restrict__ out,
                                                       int base) {
    apply_body(src, out, base + blockIdx.y, blockIdx.x, (int)gridDim.x, threadIdx.x);
}

extern "C" void kernel_launch(void* const* d_in, const int* in_sizes, int n_in,
                              void* d_out, int out_size) {
    const float* src = (const float*)d_in[0];
    const float* dst = (const float*)d_in[1];
    float* out = (float*)d_out;

    zero_kernel<<<2, 256>>>();

    // Prologue: reduce batches 0..1 (148 blocks/batch, ~3.46 v8 iters)
    dim3 rgrid(148, BPG);
    reduce_kernel<<<rgrid, TPB>>>(src, dst, 0);

    // Pipeline: combined(p) applies group p and reduces group p+1
    dim3 cgrid(2 * GXC, 2);
    for (int p = 0; p < NGROUP - 1; p++)
        combined_kernel<<<cgrid, TPB>>>(src, dst, out, p * BPG);

    // Epilogue: apply final group
    dim3 agrid(148, BPG);
    apply_kernel<<<agrid, TPB>>>(src, out, (NGROUP - 1) * BPG);
}

// round 16
// speedup vs baseline: 1.0153x; 1.0153x over previous
#include <cuda_runtime.h>

#define BATCH 16
#define NPIX (1024 * 1024)
#define NVEC (NPIX / 4)
#define NV8  (NPIX / 8)
#define NACC 21
#define BPG 2                     // pipeline group size: <=48 MB evict_last live set
#define NGROUP (BATCH / BPG)      // 8 groups
#define TPB 256
#define APB 160                   // combined: apply blocks per batch  (320 total)
#define RPB 62                    // combined: reduce blocks per batch (124 total)
#define CGRID (2 * APB + 2 * RPB) // 444 = 3/SM single wave

// Scratch (allocation-free per harness rules)
__device__ double g_acc[BATCH][NACC];

__global__ void zero_kernel() {
    int i = blockIdx.x * blockDim.x + threadIdx.x;
    if (i < BATCH * NACC) ((double*)g_acc)[i] = 0.0;
}

// 256-bit loads with L2 eviction priority (sm_103 requires .v8.b32 for these hints)
struct f8 { float4 a, b; };

__device__ __forceinline__ f8 ld8_last(const float* p) {   // pin in L2
    f8 v;
    asm("ld.global.L2::evict_last.v8.b32 {%0,%1,%2,%3,%4,%5,%6,%7}, [%8];"
        : "=f"(v.a.x), "=f"(v.a.y), "=f"(v.a.z), "=f"(v.a.w),
          "=f"(v.b.x), "=f"(v.b.y), "=f"(v.b.z), "=f"(v.b.w)
        : "l"(p));
    return v;
}
__device__ __forceinline__ f8 ld8_first(const float* p) {  // stream through L2
    f8 v;
    asm("ld.global.L2::evict_first.v8.b32 {%0,%1,%2,%3,%4,%5,%6,%7}, [%8];"
        : "=f"(v.a.x), "=f"(v.a.y), "=f"(v.a.z), "=f"(v.a.w),
          "=f"(v.b.x), "=f"(v.b.y), "=f"(v.b.z), "=f"(v.b.w)
        : "l"(p));
    return v;
}

// ---------------- device bodies ----------------

__device__ __forceinline__ void reduce_body(const float* __restrict__ src,
                                            const float* __restrict__ dst,
                                            int b, int blk, int nblk, int tid) {
    const float* A0 = src + (size_t)b * 3 * NPIX;
    const float* A1 = A0 + NPIX;
    const float* A2 = A1 + NPIX;
    const float* B0 = dst + (size_t)b * 3 * NPIX;
    const float* B1 = B0 + NPIX;
    const float* B2 = B1 + NPIX;

    float acc[NACC];
#pragma unroll
    for (int k = 0; k < NACC; k++) acc[k] = 0.0f;

    const int stride = nblk * TPB;
    for (int i = blk * TPB + tid; i < NV8; i += stride) {
        const int e = i * 8;
        f8 a0 = ld8_last(A0 + e), a1 = ld8_last(A1 + e), a2 = ld8_last(A2 + e);
        f8 b0 = ld8_first(B0 + e), b1 = ld8_first(B1 + e), b2 = ld8_first(B2 + e);
#define LANE(h, c)                                                              \
        {                                                                       \
            float x0 = a0.h.c, x1 = a1.h.c, x2 = a2.h.c;                        \
            float y0 = b0.h.c, y1 = b1.h.c, y2 = b2.h.c;                        \
            acc[0] += x0;  acc[1] += x1;  acc[2] += x2;                         \
            acc[3] += y0;  acc[4] += y1;  acc[5] += y2;                         \
            acc[6]  += x0 * x0; acc[7]  += x0 * x1; acc[8]  += x0 * x2;         \
            acc[9]  += x1 * x1; acc[10] += x1 * x2; acc[11] += x2 * x2;         \
            acc[12] += y0 * x0; acc[13] += y0 * x1; acc[14] += y0 * x2;         \
            acc[15] += y1 * x0; acc[16] += y1 * x1; acc[17] += y1 * x2;         \
            acc[18] += y2 * x0; acc[19] += y2 * x1; acc[20] += y2 * x2;         \
        }
        LANE(a, x) LANE(a, y) LANE(a, z) LANE(a, w)
        LANE(b, x) LANE(b, y) LANE(b, z) LANE(b, w)
#undef LANE
    }

    __shared__ float s[NACC][TPB / 32];
    const int lane = tid & 31;
    const int warp = tid >> 5;
#pragma unroll
    for (int k = 0; k < NACC; k++) {
        float v = acc[k];
#pragma unroll
        for (int o = 16; o > 0; o >>= 1) v += __shfl_down_sync(0xffffffffu, v, o);
        if (lane == 0) s[k][warp] = v;
    }
    __syncthreads();
    if (tid < NACC) {
        float v = 0.0f;
#pragma unroll
        for (int w = 0; w < TPB / 32; w++) v += s[tid][w];
        atomicAdd(&g_acc[b][tid], (double)v);
    }
}

__device__ __forceinline__ void apply_body(const float* __restrict__ src,
                                           float* __restrict__ out,
                                           int b, int blk, int nblk, int tid) {
    __shared__ float sh_coef[12];
    if (tid == 0) {
        const double* a = g_acc[b];
        const double n = (double)NPIX;
        double mA[3] = {a[0] / n, a[1] / n, a[2] / n};
        double mB[3] = {a[3] / n, a[4] / n, a[5] / n};
        double AA[3][3];
        AA[0][0] = a[6]  - n * mA[0] * mA[0] + 0.001;
        AA[0][1] = a[7]  - n * mA[0] * mA[1];
        AA[0][2] = a[8]  - n * mA[0] * mA[2];
        AA[1][1] = a[9]  - n * mA[1] * mA[1] + 0.001;
        AA[1][2] = a[10] - n * mA[1] * mA[2];
        AA[2][2] = a[11] - n * mA[2] * mA[2] + 0.001;
        AA[1][0] = AA[0][1]; AA[2][0] = AA[0][2]; AA[2][1] = AA[1][2];
        double BA[3][3];
#pragma unroll
        for (int i = 0; i < 3; i++)
#pragma unroll
            for (int j = 0; j < 3; j++)
                BA[i][j] = a[12 + 3 * i + j] - n * mB[i] * mA[j];

        double c00 =  (AA[1][1] * AA[2][2] - AA[1][2] * AA[2][1]);
        double c01 = -(AA[1][0] * AA[2][2] - AA[1][2] * AA[2][0]);
        double c02 =  (AA[1][0] * AA[2][1] - AA[1][1] * AA[2][0]);
        double c10 = -(AA[0][1] * AA[2][2] - AA[0][2] * AA[2][1]);
        double c11 =  (AA[0][0] * AA[2][2] - AA[0][2] * AA[2][0]);
        double c12 = -(AA[0][0] * AA[2][1] - AA[0][1] * AA[2][0]);
        double c20 =  (AA[0][1] * AA[1][2] - AA[0][2] * AA[1][1]);
        double c21 = -(AA[0][0] * AA[1][2] - AA[0][2] * AA[1][0]);
        double c22 =  (AA[0][0] * AA[1][1] - AA[0][1] * AA[1][0]);
        double det = AA[0][0] * c00 + AA[0][1] * c01 + AA[0][2] * c02;
        double id = 1.0 / det;
        double inv[3][3] = {{c00 * id, c10 * id, c20 * id},
                            {c01 * id, c11 * id, c21 * id},
                            {c02 * id, c12 * id, c22 * id}};
#pragma unroll
        for (int i = 0; i < 3; i++) {
            double xi[3];
#pragma unroll
            for (int j = 0; j < 3; j++)
                xi[j] = BA[i][0] * inv[0][j] + BA[i][1] * inv[1][j] + BA[i][2] * inv[2][j];
            sh_coef[3 * i + 0] = (float)xi[0];
            sh_coef[3 * i + 1] = (float)xi[1];
            sh_coef[3 * i + 2] = (float)xi[2];
            sh_coef[9 + i] = (float)(mB[i] - (xi[0] * mA[0] + xi[1] * mA[1] + xi[2] * mA[2]));
        }
    }
    __syncthreads();

    const float x00 = sh_coef[0], x01 = sh_coef[1], x02 = sh_coef[2];
    const float x10 = sh_coef[3], x11 = sh_coef[4], x12 = sh_coef[5];
    const float x20 = sh_coef[6], x21 = sh_coef[7], x22 = sh_coef[8];
    const float o0 = sh_coef[9], o1 = sh_coef[10], o2 = sh_coef[11];

    const float4* A0 = (const float4*)(src + (size_t)b * 3 * NPIX);
    const float4* A1 = A0 + NVEC;
    const float4* A2 = A1 + NVEC;
    float4* O0 = (float4*)(out + (size_t)b * 3 * NPIX);
    float4* O1 = O0 + NVEC;
    float4* O2 = O1 + NVEC;

    const int stride = nblk * TPB;
    for (int i = blk * TPB + tid; i < NVEC; i += stride) {
        // src pinned by the previous launch's evict_last loads; .cs demotes on use
        float4 a0 = __ldcs(A0 + i), a1 = __ldcs(A1 + i), a2 = __ldcs(A2 + i);
        float4 r0, r1, r2;
#define LANE(c)                                                \
        r0.c = x00 * a0.c + x01 * a1.c + x02 * a2.c + o0;      \
        r1.c = x10 * a0.c + x11 * a1.c + x12 * a2.c + o1;      \
        r2.c = x20 * a0.c + x21 * a1.c + x22 * a2.c + o2;
        LANE(x) LANE(y) LANE(z) LANE(w)
#undef LANE
        __stcs(O0 + i, r0);
        __stcs(O1 + i, r1);
        __stcs(O2 + i, r2);
    }
}

// ---------------- kernels ----------------

// Prologue: reduce group 0 only.
__global__ void __launch_bounds__(TPB, 3) reduce_kernel(const float* __restrict__ src,
                                                        const float* __restrict__ dst,
                                                        int base) {
    reduce_body(src, dst, base + blockIdx.y, blockIdx.x, (int)gridDim.x, threadIdx.x);
}

// Pipelined stage: apply group base (APB blocks/batch, ~6.4 v4 iters) overlapped
// with reduce of group base+BPG (RPB blocks/batch, ~8.26 v8 iters).
// 1D grid of 444 blocks = 3/SM single wave:
//   [0, APB)            apply batch base
//   [APB, 2*APB)        apply batch base+1
//   [2*APB, 2*APB+RPB)  reduce batch base+2
//   [.., CGRID)         reduce batch base+3
__global__ void __launch_bounds__(TPB, 3) combined_kernel(const float* __restrict__ src,
                                                          const float* __restrict__ dst,
                                                          float* __restrict__ out,
                                                          int base) {
    int bx = blockIdx.x;
    if (bx < 2 * APB) {
        const int half = (bx >= APB) ? 1 : 0;
        apply_body(src, out, base + half, bx - half * APB, APB, threadIdx.x);
    } else {
        bx -= 2 * APB;
        const int half = (bx >= RPB) ? 1 : 0;
        reduce_body(src, dst, base + BPG + half, bx - half * RPB, RPB, threadIdx.x);
    }
}

// Epilogue: apply final group.
__global__ void __launch_bounds__(TPB, 3) apply_kernel(const float* __restrict__ src,
                                                       float* __restrict__ out,
                                                       int base) {
    apply_body(src, out, base + blockIdx.y, blockIdx.x, (int)gridDim.x, threadIdx.x);
}

extern "C" void kernel_launch(void* const* d_in, const int* in_sizes, int n_in,
                              void* d_out, int out_size) {
    const float* src = (const float*)d_in[0];
    const float* dst = (const float*)d_in[1];
    float* out = (float*)d_out;

    zero_kernel<<<2, 256>>>();

    // Prologue: reduce batches 0..1
    dim3 rgrid(148, BPG);
    reduce_kernel<<<rgrid, TPB>>>(src, dst, 0);

    // Pipeline: combined(p) applies group p and reduces group p+1
    for (int p = 0; p < NGROUP - 1; p++)
        combined_kernel<<<CGRID, TPB>>>(src, dst, out, p * BPG);

    // Epilogue: apply final group
    dim3 agrid(148, BPG);
    apply_kernel<<<agrid, TPB>>>(src, out, (NGROUP - 1) * BPG);
}